// round 12
// baseline (speedup 1.0000x reference)
#include <cuda_runtime.h>
#include <cuda_bf16.h>
#include <math.h>
#include <stdint.h>

#define B 32
#define H 21
#define W 180
#define PIX (H*W)
#define FEAT (192*PIX)
#define NS2 180
#define KC2 (FEAT/NS2)
#define DPI 3.14159265358979323846

__device__ float g_x1[B*64*PIX];
__device__ float g_x2[B*64*PIX];
__device__ float g_x3[B*64*PIX];
__device__ float g_x4[B*64*PIX];
__device__ float g_x5[B*128*PIX];
__device__ float g_x6[B*192*PIX];
__device__ uint32_t g_wfrag[819200];   // bf16x2 A-frags: L1..L4 @ l*102400 (lo +51200), L5 @ 409600 (lo +102400 within each mh part? see pack)
__device__ float g_part[4*NS2*4096];
__device__ float g_h1[B*500];
__device__ float g_h2[B*200];
__device__ float g_h3[B*50];
__device__ float g_phi[64];
__device__ float g_trig[720];

// ---------------- helpers ----------------
__device__ __forceinline__ uint32_t tf32u(float x) {
    uint32_t u; asm("cvt.rna.tf32.f32 %0, %1;" : "=r"(u) : "f"(x)); return u;
}
__device__ __forceinline__ void mma_tf32(float* c, const uint32_t* a, const uint32_t* b) {
    asm("mma.sync.aligned.m16n8k8.row.col.f32.tf32.tf32.f32 "
        "{%0,%1,%2,%3},{%4,%5,%6,%7},{%8,%9},{%0,%1,%2,%3};"
        : "+f"(c[0]), "+f"(c[1]), "+f"(c[2]), "+f"(c[3])
        : "r"(a[0]), "r"(a[1]), "r"(a[2]), "r"(a[3]), "r"(b[0]), "r"(b[1]));
}
__device__ __forceinline__ void mma_bf16(float* c, const uint32_t* a, const uint32_t* b) {
    asm("mma.sync.aligned.m16n8k16.row.col.f32.bf16.bf16.f32 "
        "{%0,%1,%2,%3},{%4,%5,%6,%7},{%8,%9},{%0,%1,%2,%3};"
        : "+f"(c[0]), "+f"(c[1]), "+f"(c[2]), "+f"(c[3])
        : "r"(a[0]), "r"(a[1]), "r"(a[2]), "r"(a[3]), "r"(b[0]), "r"(b[1]));
}
__device__ __forceinline__ void bf16split(float v, uint16_t& h, uint16_t& l) {
    __nv_bfloat16 hb = __float2bfloat16(v);
    float hf = __bfloat162float(hb);
    __nv_bfloat16 lb = __float2bfloat16(v - hf);
    h = __bfloat16_as_ushort(hb); l = __bfloat16_as_ushort(lb);
}

// ---------------- fused prologue: tables + bf16 A-frag pack ----------------------
// frag layout per layer: hi[kpos 25][chunk IC/16][mtile 4][lane 32][reg 4], lo at +WSZ.
// reg mapping (m16n8k16 A): row=(ln>>2)+(reg&1)*8; k0=2*(ln&3)+(reg>>1)*8.
__global__ void init_all(const float* __restrict__ w1, const float* __restrict__ w2,
                         const float* __restrict__ w3, const float* __restrict__ w4,
                         const float* __restrict__ w5, uint32_t* __restrict__ frag,
                         float* __restrict__ phi, float* __restrict__ trig)
{
    int idx = blockIdx.x * blockDim.x + threadIdx.x;
    if (idx == 0) {
        double beta = 2.28e-11, L = sqrt(51.0 / beta), spi = sqrt(DPI);
        double n0 = sqrt(spi), n1 = sqrt(2.0 * spi), n2 = sqrt(8.0 * spi);
        for (int i = 0; i < 21; i++) {
            double y = (20.0 - 2.0 * i) * 110000.0 / L;
            double e = exp(-y * y / 2.0);
            phi[i]      = (float)(e / n0);
            phi[21 + i] = (float)(e * 2.0 * y / n1);
            phi[42 + i] = (float)(e * (4.0 * y * y - 2.0) / n2);
        }
        phi[63] = (float)(2.0 * 110000.0 / L);
        for (int n = 0; n < 180; n++) {
            double t = 2.0 * DPI * n / 180.0;
            trig[n] = (float)cos(t); trig[180 + n] = (float)sin(t);
            trig[360 + n] = (float)cos(2 * t); trig[540 + n] = (float)sin(2 * t);
        }
    }
    if (idx >= 409600) return;
    const float* w; int IC, t, mh = 0, base, WSZ;
    if (idx < 204800) {
        int l = idx / 51200; t = idx % 51200;
        w = l == 0 ? w1 : l == 1 ? w2 : l == 2 ? w3 : w4;
        IC = 64; base = l * 102400; WSZ = 51200;
    } else {
        int q = idx - 204800;
        mh = q / 102400; t = q % 102400;
        w = w5; IC = 128; base = 409600 + mh * 204800; WSZ = 102400;
    }
    int CH = IC / 16, P = CH * 512;
    int kpos = t / P; int r = t % P;
    int ck = r / 512; int r2 = r % 512;
    int mtile = r2 >> 7; int ln = (r2 >> 2) & 31; int reg = r2 & 3;
    int row = (ln >> 2) + (reg & 1) * 8;
    int k0  = 2 * (ln & 3) + (reg >> 1) * 8;
    int oc = mh * 64 + mtile * 16 + row;
    int ic = ck * 16 + k0;
    float v0 = w[((size_t)oc * IC + ic) * 25 + kpos];
    float v1 = w[((size_t)oc * IC + ic + 1) * 25 + kpos];
    uint16_t h0, l0, h1, l1;
    bf16split(v0, h0, l0); bf16split(v1, h1, l1);
    frag[base + t]       = (uint32_t)h0 | ((uint32_t)h1 << 16);
    frag[base + WSZ + t] = (uint32_t)l0 | ((uint32_t)l1 << 16);
}

// ---------------- conv_in: 1->64, naive fp32 -------------------------------------
__global__ void conv_in_k(const float* __restrict__ x, const float* __restrict__ w,
                          const float* __restrict__ bias, float* __restrict__ out)
{
    int idx = blockIdx.x * blockDim.x + threadIdx.x;
    if (idx >= B * 64 * PIX) return;
    int px = idx % PIX, oc = (idx / PIX) & 63, b = idx / (64 * PIX);
    int y = px / W, xx = px % W;
    const float* ip = x + (size_t)b * PIX;
    const float* wp = w + oc * 25;
    float s = bias[oc];
#pragma unroll
    for (int kh = 0; kh < 5; kh++) {
        int gy = y + kh - 2;
        if (gy < 0 || gy >= H) continue;
#pragma unroll
        for (int kw = 0; kw < 5; kw++) {
            int gx = xx + kw - 2;
            if (gx >= 0 && gx < W) s = fmaf(ip[gy * W + gx], wp[kh * 5 + kw], s);
        }
    }
    out[idx] = fmaxf(s, 0.f);
}

// ---------------- tensor conv: 3-term bf16 split, m16n8k16, term-reordered -------
// Tile M=64 oc x N=96 px; K = IC*25 via 16-ic chunks. Input smem bf16x2 pairs,
// pair-stride 520 == 8 mod 32 (conflict-free). Weights staged in A-frag order.
// MMA issue order: 6x AhBh, 6x AhBl, 6x AlBh -> same-acc reuse 6 instrs apart.
template<int IC>
__global__ __launch_bounds__(256, 3)
void conv_mma(const float* __restrict__ in, const uint32_t* __restrict__ wfrag,
              const float* __restrict__ bias,
              float* __restrict__ out, int outCtot,
              float* __restrict__ out2, int out2Ctot, int out2Off)
{
    constexpr int CH = IC / 16;
    constexpr int WSZ = 25 * CH * 512;
    constexpr int XS = 520, RS = 104;
    extern __shared__ uint32_t smu[];
    uint32_t* sInH = smu;             // 4160
    uint32_t* sInL = smu + 4160;      // 4160
    uint32_t* sWh  = smu + 8320;      // 2560
    uint32_t* sWl  = smu + 10880;     // 2560 (13440 u32 = 53760 B)

    int tid = threadIdx.x, lane = tid & 31, warpId = tid >> 5;
    int wm = warpId >> 2, wn = warpId & 3;
    int xh = blockIdx.x & 1, mh = blockIdx.x >> 1;
    int y = blockIdx.y, b = blockIdx.z;
    int x0 = xh * 96;
    const uint32_t* wH = wfrag + mh * 2 * WSZ;
    const uint32_t* wL = wH + WSZ;

    float c[2][3][4] = {};
    int p = warpId;

#pragma unroll 1
    for (int ch = 0; ch < CH; ch++) {
        __syncthreads();
        {   // input tile: 8 icpairs x 5 rows x 104, split+packed bf16x2
            const float* in0 = in + (size_t)(b * IC + ch * 16 + 2 * p) * PIX;
            const float* in1 = in0 + PIX;
            uint32_t* dH = sInH + p * XS;
            uint32_t* dL = sInL + p * XS;
#pragma unroll
            for (int r = 0; r < 5; r++) {
                int gy = y + r - 2;
                bool okY = (gy >= 0 && gy < H);
#pragma unroll
                for (int xx = lane; xx < RS; xx += 32) {
                    int gx = x0 - 2 + xx;
                    float v0 = 0.f, v1 = 0.f;
                    if (okY && gx >= 0 && gx < W) {
                        v0 = in0[gy * W + gx];
                        v1 = in1[gy * W + gx];
                    }
                    uint16_t h0, l0, h1, l1;
                    bf16split(v0, h0, l0); bf16split(v1, h1, l1);
                    dH[r * RS + xx] = (uint32_t)h0 | ((uint32_t)h1 << 16);
                    dL[r * RS + xx] = (uint32_t)l0 | ((uint32_t)l1 << 16);
                }
            }
        }
#pragma unroll 1
        for (int kh = 0; kh < 5; kh++) {
            __syncthreads();
            for (int i = tid; i < 2560; i += 256) {
                int kw = i >> 9, off = i & 511;
                int src = ((kh * 5 + kw) * CH + ch) * 512 + off;
                sWh[i] = wH[src];
                sWl[i] = wL[src];
            }
            __syncthreads();
#pragma unroll
            for (int kw = 0; kw < 5; kw++) {
                uint32_t ah[2][4], al[2][4];
#pragma unroll
                for (int mt = 0; mt < 2; mt++) {
                    int base = (kw * 4 + wm * 2 + mt) * 128 + lane * 4;
                    *(uint4*)ah[mt] = *(const uint4*)&sWh[base];
                    *(uint4*)al[mt] = *(const uint4*)&sWl[base];
                }
                int bbase = (lane & 3) * XS + kh * RS + wn * 24 + (lane >> 2) + kw;
                uint32_t bh[3][2], bl[3][2];
#pragma unroll
                for (int nt = 0; nt < 3; nt++) {
                    int bi = bbase + nt * 8;
                    bh[nt][0] = sInH[bi]; bh[nt][1] = sInH[bi + 4 * XS];
                    bl[nt][0] = sInL[bi]; bl[nt][1] = sInL[bi + 4 * XS];
                }
                // term 1: Ah*Bh (6 independent)
#pragma unroll
                for (int mt = 0; mt < 2; mt++)
#pragma unroll
                    for (int nt = 0; nt < 3; nt++)
                        mma_bf16(c[mt][nt], ah[mt], bh[nt]);
                // term 2: Ah*Bl
#pragma unroll
                for (int mt = 0; mt < 2; mt++)
#pragma unroll
                    for (int nt = 0; nt < 3; nt++)
                        mma_bf16(c[mt][nt], ah[mt], bl[nt]);
                // term 3: Al*Bh
#pragma unroll
                for (int mt = 0; mt < 2; mt++)
#pragma unroll
                    for (int nt = 0; nt < 3; nt++)
                        mma_bf16(c[mt][nt], al[mt], bh[nt]);
            }
        }
    }

    // epilogue: bias + relu + store, optional concat dual-write
    int ocL = mh * 64 + wm * 32;
#pragma unroll
    for (int mt = 0; mt < 2; mt++) {
        int ocRow = ocL + mt * 16 + (lane >> 2);
        float bv0 = bias[ocRow], bv8 = bias[ocRow + 8];
#pragma unroll
        for (int nt = 0; nt < 3; nt++) {
            int x = x0 + wn * 24 + nt * 8 + (lane & 3) * 2;
            if (x < W) {
                float2 v0 = make_float2(fmaxf(c[mt][nt][0] + bv0, 0.f),
                                        fmaxf(c[mt][nt][1] + bv0, 0.f));
                float2 v1 = make_float2(fmaxf(c[mt][nt][2] + bv8, 0.f),
                                        fmaxf(c[mt][nt][3] + bv8, 0.f));
                size_t o0 = ((size_t)(b * outCtot + ocRow) * H + y) * W + x;
                size_t o1 = o0 + (size_t)8 * H * W;
                *(float2*)&out[o0] = v0;
                *(float2*)&out[o1] = v1;
                if (out2) {
                    size_t q0 = ((size_t)(b * out2Ctot + out2Off + ocRow) * H + y) * W + x;
                    size_t q1 = q0 + (size_t)8 * H * W;
                    *(float2*)&out2[q0] = v0;
                    *(float2*)&out2[q1] = v1;
                }
            }
        }
    }
}

// ---------------- fused Hermite + Fourier residual, single pass ------------------
// One block per (b,c) plane. Phase 1: 180 threads do lat-projection per column
// into smem. Phase 2: 6 warps do lon-projection per row, write once.
__global__ __launch_bounds__(192)
void filter_fused(float* __restrict__ x, const float* __restrict__ phi,
                  const float* __restrict__ trig)
{
    __shared__ float sp[21][181];
    int tid = threadIdx.x, wid = tid >> 5, lane = tid & 31;
    float* base = x + (size_t)blockIdx.x * PIX;

    if (tid < 180) {
        float v[21];
#pragma unroll
        for (int y = 0; y < 21; y++) v[y] = base[y * W + tid];
        float dy = phi[63], u0 = 0.f, u1 = 0.f, u2 = 0.f;
#pragma unroll
        for (int y = 0; y < 21; y++) {
            u0 += v[y] * phi[y]; u1 += v[y] * phi[21 + y]; u2 += v[y] * phi[42 + y];
        }
        u0 *= dy; u1 *= dy; u2 *= dy;
#pragma unroll
        for (int y = 0; y < 21; y++)
            sp[y][tid] = v[y] - (u0 * phi[y] + u1 * phi[21 + y] + u2 * phi[42 + y]);
    }
    __syncthreads();

    const float* c1 = trig, *s1 = trig + 180, *c2 = trig + 360, *s2 = trig + 540;
    const float inv = 1.f / 180.f, inv2 = 2.f / 180.f;
#pragma unroll 1
    for (int y = wid; y < 21; y += 6) {
        float q0 = 0.f, q1 = 0.f, q2 = 0.f, q3 = 0.f, q4 = 0.f;
#pragma unroll
        for (int t = 0; t < 6; t++) {
            int n = t * 32 + lane;
            if (n < W) {
                float xv = sp[y][n];
                q0 += xv; q1 += xv * c1[n]; q2 += xv * s1[n];
                q3 += xv * c2[n]; q4 += xv * s2[n];
            }
        }
#pragma unroll
        for (int o = 16; o; o >>= 1) {
            q0 += __shfl_xor_sync(~0u, q0, o); q1 += __shfl_xor_sync(~0u, q1, o);
            q2 += __shfl_xor_sync(~0u, q2, o); q3 += __shfl_xor_sync(~0u, q3, o);
            q4 += __shfl_xor_sync(~0u, q4, o);
        }
#pragma unroll
        for (int t = 0; t < 6; t++) {
            int n = t * 32 + lane;
            if (n < W)
                base[y * W + n] = sp[y][n] - q0 * inv
                    - inv2 * (q1 * c1[n] + q2 * s1[n] + q3 * c2[n] + q4 * s2[n]);
        }
    }
}

// ---------------- FC1 via tf32 mma, split-K=180 ----------------------------------
__global__ __launch_bounds__(256)
void fc1_mma(const float* __restrict__ act, const float* __restrict__ w,
             float* __restrict__ part)
{
    int tid = threadIdx.x, lane = tid & 31, wid = tid >> 5;
    int ks = blockIdx.x, jg = blockIdx.y;
    int r = lane >> 2, cc = lane & 3;
    int j0 = jg * 128 + wid * 16 + r, j1 = j0 + 8;
    bool ok0 = j0 < 500, ok1 = j1 < 500;
    const float* w0 = w + (size_t)j0 * FEAT;
    const float* w1 = w + (size_t)j1 * FEAT;
    const float* a0 = act + (size_t)r * FEAT;
    const float* a1 = a0 + (size_t)8 * FEAT;
    const float* a2 = a0 + (size_t)16 * FEAT;
    const float* a3 = a0 + (size_t)24 * FEAT;
    int kb = ks * KC2;
    float acc[4][4] = {};
#pragma unroll 2
    for (int k = kb; k < kb + KC2; k += 8) {
        uint32_t a[4];
        a[0] = ok0 ? tf32u(w0[k + cc]) : 0u;
        a[1] = ok1 ? tf32u(w1[k + cc]) : 0u;
        a[2] = ok0 ? tf32u(w0[k + 4 + cc]) : 0u;
        a[3] = ok1 ? tf32u(w1[k + 4 + cc]) : 0u;
        uint32_t bb[2];
        bb[0] = tf32u(a0[k + cc]); bb[1] = tf32u(a0[k + 4 + cc]); mma_tf32(acc[0], a, bb);
        bb[0] = tf32u(a1[k + cc]); bb[1] = tf32u(a1[k + 4 + cc]); mma_tf32(acc[1], a, bb);
        bb[0] = tf32u(a2[k + cc]); bb[1] = tf32u(a2[k + 4 + cc]); mma_tf32(acc[2], a, bb);
        bb[0] = tf32u(a3[k + cc]); bb[1] = tf32u(a3[k + 4 + cc]); mma_tf32(acc[3], a, bb);
    }
    float* pp = part + (size_t)(jg * NS2 + ks) * 4096;
    int jr = wid * 16 + r;
#pragma unroll
    for (int nt = 0; nt < 4; nt++) {
        int bc = nt * 8 + 2 * cc;
        pp[jr * 32 + bc]           = acc[nt][0];
        pp[jr * 32 + bc + 1]       = acc[nt][1];
        pp[(jr + 8) * 32 + bc]     = acc[nt][2];
        pp[(jr + 8) * 32 + bc + 1] = acc[nt][3];
    }
}

__global__ void fc1_reduce(const float* __restrict__ part, const float* __restrict__ bias,
                           float* __restrict__ h1)
{
    int idx = blockIdx.x * blockDim.x + threadIdx.x;
    if (idx >= 32 * 512) return;
    int b = idx & 31, j = idx >> 5;
    if (j >= 500) return;
    int jg = j >> 7, jr = j & 127;
    float s = bias[j];
    const float* pp = part + (size_t)jg * NS2 * 4096 + jr * 32 + b;
    for (int k = 0; k < NS2; k++) s += pp[(size_t)k * 4096];
    h1[b * 500 + j] = s;
}

__global__ void fc_small(const float* __restrict__ in, const float* __restrict__ w,
                         const float* __restrict__ bias, float* __restrict__ out,
                         int N, int K, int reluIn, int reluOut)
{
    int idx = blockIdx.x * blockDim.x + threadIdx.x;
    if (idx >= 32 * N) return;
    int b = idx / N, n = idx % N;
    float s = bias[n];
    const float* ip = in + b * K;
    const float* wp = w + n * K;
    for (int k = 0; k < K; k++) {
        float a = ip[k];
        if (reluIn) a = fmaxf(a, 0.f);
        s = fmaf(a, wp[k], s);
    }
    if (reluOut) s = fmaxf(s, 0.f);
    out[idx] = s;
}

// ---------------- host launcher ----------------
extern "C" void kernel_launch(void* const* d_in, const int* in_sizes, int n_in,
                              void* d_out, int out_size)
{
    const float* x    = (const float*)d_in[0];
    const float* w_in = (const float*)d_in[1];
    const float* b_in = (const float*)d_in[2];
    const float* w1 = (const float*)d_in[3],  *b1 = (const float*)d_in[4];
    const float* w2 = (const float*)d_in[5],  *b2 = (const float*)d_in[6];
    const float* w3 = (const float*)d_in[7],  *b3 = (const float*)d_in[8];
    const float* w4 = (const float*)d_in[9],  *b4 = (const float*)d_in[10];
    const float* w5 = (const float*)d_in[11], *b5 = (const float*)d_in[12];
    const float* wfc1 = (const float*)d_in[13], *bfc1 = (const float*)d_in[14];
    const float* wfc2 = (const float*)d_in[15], *bfc2 = (const float*)d_in[16];
    const float* wfc3 = (const float*)d_in[17], *bfc3 = (const float*)d_in[18];
    const float* wfc4 = (const float*)d_in[19], *bfc4 = (const float*)d_in[20];
    float* out = (float*)d_out;

    float *x1, *x2, *x3, *x4, *x5, *x6, *part, *h1, *h2, *h3, *phi, *trig;
    uint32_t* wfrag;
    cudaGetSymbolAddress((void**)&x1, g_x1);
    cudaGetSymbolAddress((void**)&x2, g_x2);
    cudaGetSymbolAddress((void**)&x3, g_x3);
    cudaGetSymbolAddress((void**)&x4, g_x4);
    cudaGetSymbolAddress((void**)&x5, g_x5);
    cudaGetSymbolAddress((void**)&x6, g_x6);
    cudaGetSymbolAddress((void**)&wfrag, g_wfrag);
    cudaGetSymbolAddress((void**)&part, g_part);
    cudaGetSymbolAddress((void**)&h1, g_h1);
    cudaGetSymbolAddress((void**)&h2, g_h2);
    cudaGetSymbolAddress((void**)&h3, g_h3);
    cudaGetSymbolAddress((void**)&phi, g_phi);
    cudaGetSymbolAddress((void**)&trig, g_trig);

    const int smem_c = 13440 * 4;                        // 53760 -> 3 CTAs/SM
    cudaFuncSetAttribute(conv_mma<64>,
                         cudaFuncAttributeMaxDynamicSharedMemorySize, smem_c);
    cudaFuncSetAttribute(conv_mma<128>,
                         cudaFuncAttributeMaxDynamicSharedMemorySize, smem_c);

    // L0: fused prologue (tables + A-frag pack)
    init_all<<<1600, 256>>>(w1, w2, w3, w4, w5, wfrag, phi, trig);
    // L1: conv_in (fp32, tiny)
    conv_in_k<<<(B * 64 * PIX + 255) / 256, 256>>>(x, w_in, b_in, x1);

    // L2-L6: tensor convs; concat fused via dual-write. L5 = conv4 (ncu -s 5 target)
    dim3 gm(2, 21, B);
    conv_mma<64><<<gm, 256, smem_c>>>(x1, wfrag,          b1, x2, 64,  x6, 192, 128);
    conv_mma<64><<<gm, 256, smem_c>>>(x2, wfrag + 102400, b2, x3, 64,  x5, 128, 64);
    conv_mma<64><<<gm, 256, smem_c>>>(x3, wfrag + 204800, b3, x4, 64,  nullptr, 0, 0);
    conv_mma<64><<<gm, 256, smem_c>>>(x4, wfrag + 307200, b4, x5, 128, nullptr, 0, 0);
    conv_mma<128><<<dim3(4, 21, B), 256, smem_c>>>(x5, wfrag + 409600, b5, x6, 192,
                                                   nullptr, 0, 0);

    // L7: fused residual filters (single pass)
    filter_fused<<<B * 192, 192>>>(x6, phi, trig);

    // FC stack
    fc1_mma<<<dim3(NS2, 4), 256>>>(x6, wfc1, part);
    fc1_reduce<<<64, 256>>>(part, bfc1, h1);
    fc_small<<<(32 * 200 + 255) / 256, 256>>>(h1, wfc2, bfc2, h2, 200, 500, 1, 1);
    fc_small<<<(32 * 50 + 255) / 256, 256>>>(h2, wfc3, bfc3, h3, 50, 200, 0, 1);
    fc_small<<<1, 64>>>(h3, wfc4, bfc4, out, 2, 50, 0, 0);
}

// round 14
// speedup vs baseline: 1.0966x; 1.0966x over previous
#include <cuda_runtime.h>
#include <cuda_bf16.h>
#include <math.h>
#include <stdint.h>

#define B 32
#define H 21
#define W 180
#define PIX (H*W)
#define FEAT (192*PIX)
#define NS2 180
#define KC2 (FEAT/NS2)
#define DPI 3.14159265358979323846

__device__ float g_x1[B*64*PIX];
__device__ float g_x2[B*64*PIX];
__device__ float g_x3[B*64*PIX];
__device__ float g_x4[B*64*PIX];
__device__ float g_x5[B*128*PIX];
__device__ float g_x6[B*192*PIX];
__device__ uint32_t g_wfrag[819200];   // bf16x2 A-frags: L1..L4 @ l*102400 (lo +51200), L5 @ 409600+mh*204800 (lo +102400)
__device__ float g_part[4*NS2*4096];
__device__ float g_h1[B*500];
__device__ float g_h2[B*200];
__device__ float g_h3[B*50];
__device__ float g_phi[64];
__device__ float g_trig[720];

// ---------------- helpers ----------------
__device__ __forceinline__ uint32_t tf32u(float x) {
    uint32_t u; asm("cvt.rna.tf32.f32 %0, %1;" : "=r"(u) : "f"(x)); return u;
}
__device__ __forceinline__ void mma_tf32(float* c, const uint32_t* a, const uint32_t* b) {
    asm("mma.sync.aligned.m16n8k8.row.col.f32.tf32.tf32.f32 "
        "{%0,%1,%2,%3},{%4,%5,%6,%7},{%8,%9},{%0,%1,%2,%3};"
        : "+f"(c[0]), "+f"(c[1]), "+f"(c[2]), "+f"(c[3])
        : "r"(a[0]), "r"(a[1]), "r"(a[2]), "r"(a[3]), "r"(b[0]), "r"(b[1]));
}
__device__ __forceinline__ void mma_bf16(float* c, const uint32_t* a, const uint32_t* b) {
    asm("mma.sync.aligned.m16n8k16.row.col.f32.bf16.bf16.f32 "
        "{%0,%1,%2,%3},{%4,%5,%6,%7},{%8,%9},{%0,%1,%2,%3};"
        : "+f"(c[0]), "+f"(c[1]), "+f"(c[2]), "+f"(c[3])
        : "r"(a[0]), "r"(a[1]), "r"(a[2]), "r"(a[3]), "r"(b[0]), "r"(b[1]));
}
__device__ __forceinline__ void bf16split(float v, uint16_t& h, uint16_t& l) {
    __nv_bfloat16 hb = __float2bfloat16(v);
    float hf = __bfloat162float(hb);
    __nv_bfloat16 lb = __float2bfloat16(v - hf);
    h = __bfloat16_as_ushort(hb); l = __bfloat16_as_ushort(lb);
}

// ---------------- fused prologue: tables + bf16 A-frag pack ----------------------
// frag layout per layer: hi[kpos 25][chunk IC/16][mtile 4][lane 32][reg 4], lo at +WSZ.
// reg mapping (m16n8k16 A): row=(ln>>2)+(reg&1)*8; k0=2*(ln&3)+(reg>>1)*8.
__global__ void init_all(const float* __restrict__ w1, const float* __restrict__ w2,
                         const float* __restrict__ w3, const float* __restrict__ w4,
                         const float* __restrict__ w5, uint32_t* __restrict__ frag,
                         float* __restrict__ phi, float* __restrict__ trig)
{
    int idx = blockIdx.x * blockDim.x + threadIdx.x;
    if (idx == 0) {
        double beta = 2.28e-11, L = sqrt(51.0 / beta), spi = sqrt(DPI);
        double n0 = sqrt(spi), n1 = sqrt(2.0 * spi), n2 = sqrt(8.0 * spi);
        for (int i = 0; i < 21; i++) {
            double y = (20.0 - 2.0 * i) * 110000.0 / L;
            double e = exp(-y * y / 2.0);
            phi[i]      = (float)(e / n0);
            phi[21 + i] = (float)(e * 2.0 * y / n1);
            phi[42 + i] = (float)(e * (4.0 * y * y - 2.0) / n2);
        }
        phi[63] = (float)(2.0 * 110000.0 / L);
        for (int n = 0; n < 180; n++) {
            double t = 2.0 * DPI * n / 180.0;
            trig[n] = (float)cos(t); trig[180 + n] = (float)sin(t);
            trig[360 + n] = (float)cos(2 * t); trig[540 + n] = (float)sin(2 * t);
        }
    }
    if (idx >= 409600) return;
    const float* w; int IC, t, mh = 0, base, WSZ;
    if (idx < 204800) {
        int l = idx / 51200; t = idx % 51200;
        w = l == 0 ? w1 : l == 1 ? w2 : l == 2 ? w3 : w4;
        IC = 64; base = l * 102400; WSZ = 51200;
    } else {
        int q = idx - 204800;
        mh = q / 102400; t = q % 102400;
        w = w5; IC = 128; base = 409600 + mh * 204800; WSZ = 102400;
    }
    int CH = IC / 16, P = CH * 512;
    int kpos = t / P; int r = t % P;
    int ck = r / 512; int r2 = r % 512;
    int mtile = r2 >> 7; int ln = (r2 >> 2) & 31; int reg = r2 & 3;
    int row = (ln >> 2) + (reg & 1) * 8;
    int k0  = 2 * (ln & 3) + (reg >> 1) * 8;
    int oc = mh * 64 + mtile * 16 + row;
    int ic = ck * 16 + k0;
    float v0 = w[((size_t)oc * IC + ic) * 25 + kpos];
    float v1 = w[((size_t)oc * IC + ic + 1) * 25 + kpos];
    uint16_t h0, l0, h1, l1;
    bf16split(v0, h0, l0); bf16split(v1, h1, l1);
    frag[base + t]       = (uint32_t)h0 | ((uint32_t)h1 << 16);
    frag[base + WSZ + t] = (uint32_t)l0 | ((uint32_t)l1 << 16);
}

// ---------------- conv_in: 1->64, naive fp32 -------------------------------------
__global__ void conv_in_k(const float* __restrict__ x, const float* __restrict__ w,
                          const float* __restrict__ bias, float* __restrict__ out)
{
    int idx = blockIdx.x * blockDim.x + threadIdx.x;
    if (idx >= B * 64 * PIX) return;
    int px = idx % PIX, oc = (idx / PIX) & 63, b = idx / (64 * PIX);
    int y = px / W, xx = px % W;
    const float* ip = x + (size_t)b * PIX;
    const float* wp = w + oc * 25;
    float s = bias[oc];
#pragma unroll
    for (int kh = 0; kh < 5; kh++) {
        int gy = y + kh - 2;
        if (gy < 0 || gy >= H) continue;
#pragma unroll
        for (int kw = 0; kw < 5; kw++) {
            int gx = xx + kw - 2;
            if (gx >= 0 && gx < W) s = fmaf(ip[gy * W + gx], wp[kh * 5 + kw], s);
        }
    }
    out[idx] = fmaxf(s, 0.f);
}

// ---------------- tensor conv: 3-term bf16 split, N=192 full row -----------------
// One CTA per (mh, y, b). M=64 oc x N=192 px. Input smem only (64KB, 2 CTAs/SM);
// weights LDG->regs (L1-resident, identical across CTAs). 2 syncs per chunk.
// RS=200 covers xx<=195 (n up to 191 + kw 4); XS=1000 == 8 mod 32 -> B-frag
// lanes (k,n) hit banks 8k+n, conflict-free.
template<int IC>
__global__ __launch_bounds__(256, 2)
void conv_mma(const float* __restrict__ in, const uint32_t* __restrict__ wfrag,
              const float* __restrict__ bias,
              float* __restrict__ out, int outCtot,
              float* __restrict__ out2, int out2Ctot, int out2Off)
{
    constexpr int CH = IC / 16;
    constexpr int WSZ = 25 * CH * 512;
    constexpr int RS = 200, XS = 5 * RS;   // 1000
    extern __shared__ uint32_t smu[];
    uint32_t* sInH = smu;             // 8000
    uint32_t* sInL = smu + 8000;      // 8000 (16000 u32 = 64000 B)

    int tid = threadIdx.x, lane = tid & 31, warpId = tid >> 5;
    int wm = warpId >> 2, wn = warpId & 3;
    int mh = blockIdx.x;
    int y = blockIdx.y, b = blockIdx.z;
    const uint32_t* wH = wfrag + mh * 2 * WSZ;
    const uint32_t* wL = wH + WSZ;

    float c[2][6][4] = {};
    int p = warpId;

#pragma unroll 1
    for (int ch = 0; ch < CH; ch++) {
        __syncthreads();
        {   // input tile: 8 icpairs x 5 rows x 200 cols, split+packed bf16x2
            const float* in0 = in + (size_t)(b * IC + ch * 16 + 2 * p) * PIX;
            const float* in1 = in0 + PIX;
            uint32_t* dH = sInH + p * XS;
            uint32_t* dL = sInL + p * XS;
#pragma unroll
            for (int r = 0; r < 5; r++) {
                int gy = y + r - 2;
                bool okY = (gy >= 0 && gy < H);
                const float* r0 = in0 + gy * W - 2;
                const float* r1 = in1 + gy * W - 2;
#pragma unroll
                for (int xx = lane; xx < RS; xx += 32) {
                    int gx = xx - 2;
                    float v0 = 0.f, v1 = 0.f;
                    if (okY && gx >= 0 && gx < W) { v0 = r0[xx]; v1 = r1[xx]; }
                    uint16_t h0, l0, h1, l1;
                    bf16split(v0, h0, l0); bf16split(v1, h1, l1);
                    dH[r * RS + xx] = (uint32_t)h0 | ((uint32_t)h1 << 16);
                    dL[r * RS + xx] = (uint32_t)l0 | ((uint32_t)l1 << 16);
                }
            }
        }
        __syncthreads();
#pragma unroll 1
        for (int kh = 0; kh < 5; kh++) {
#pragma unroll 1
            for (int kw = 0; kw < 5; kw++) {
                // A: direct LDG (L1 hit), exact frag order
                uint32_t ah[2][4], al[2][4];
                int wbase = ((kh * 5 + kw) * CH + ch) * 512 + lane * 4;
#pragma unroll
                for (int mt = 0; mt < 2; mt++) {
                    int o = wbase + (wm * 2 + mt) * 128;
                    *(uint4*)ah[mt] = *(const uint4*)&wH[o];
                    *(uint4*)al[mt] = *(const uint4*)&wL[o];
                }
                // B: gather 6 ntiles (conflict-free scalar LDS)
                int bbase = (lane & 3) * XS + kh * RS + wn * 48 + (lane >> 2) + kw;
                uint32_t bh[6][2], bl[6][2];
#pragma unroll
                for (int nt = 0; nt < 6; nt++) {
                    int bi = bbase + nt * 8;
                    bh[nt][0] = sInH[bi]; bh[nt][1] = sInH[bi + 4 * XS];
                    bl[nt][0] = sInL[bi]; bl[nt][1] = sInL[bi + 4 * XS];
                }
                // term-major issue: 12 independent accs between dependents
#pragma unroll
                for (int mt = 0; mt < 2; mt++)
#pragma unroll
                    for (int nt = 0; nt < 6; nt++)
                        mma_bf16(c[mt][nt], ah[mt], bh[nt]);
#pragma unroll
                for (int mt = 0; mt < 2; mt++)
#pragma unroll
                    for (int nt = 0; nt < 6; nt++)
                        mma_bf16(c[mt][nt], ah[mt], bl[nt]);
#pragma unroll
                for (int mt = 0; mt < 2; mt++)
#pragma unroll
                    for (int nt = 0; nt < 6; nt++)
                        mma_bf16(c[mt][nt], al[mt], bh[nt]);
            }
        }
    }

    // epilogue: bias + relu + store, optional concat dual-write
    int ocL = mh * 64 + wm * 32;
#pragma unroll
    for (int mt = 0; mt < 2; mt++) {
        int ocRow = ocL + mt * 16 + (lane >> 2);
        float bv0 = bias[ocRow], bv8 = bias[ocRow + 8];
#pragma unroll
        for (int nt = 0; nt < 6; nt++) {
            int x = wn * 48 + nt * 8 + (lane & 3) * 2;
            if (x < W) {
                float2 v0 = make_float2(fmaxf(c[mt][nt][0] + bv0, 0.f),
                                        fmaxf(c[mt][nt][1] + bv0, 0.f));
                float2 v1 = make_float2(fmaxf(c[mt][nt][2] + bv8, 0.f),
                                        fmaxf(c[mt][nt][3] + bv8, 0.f));
                size_t o0 = ((size_t)(b * outCtot + ocRow) * H + y) * W + x;
                size_t o1 = o0 + (size_t)8 * H * W;
                *(float2*)&out[o0] = v0;
                *(float2*)&out[o1] = v1;
                if (out2) {
                    size_t q0 = ((size_t)(b * out2Ctot + out2Off + ocRow) * H + y) * W + x;
                    size_t q1 = q0 + (size_t)8 * H * W;
                    *(float2*)&out2[q0] = v0;
                    *(float2*)&out2[q1] = v1;
                }
            }
        }
    }
}

// ---------------- fused Hermite + Fourier residual, single pass ------------------
__global__ __launch_bounds__(192)
void filter_fused(float* __restrict__ x, const float* __restrict__ phi,
                  const float* __restrict__ trig)
{
    __shared__ float sp[21][181];
    int tid = threadIdx.x, wid = tid >> 5, lane = tid & 31;
    float* base = x + (size_t)blockIdx.x * PIX;

    if (tid < 180) {
        float v[21];
#pragma unroll
        for (int y = 0; y < 21; y++) v[y] = base[y * W + tid];
        float dy = phi[63], u0 = 0.f, u1 = 0.f, u2 = 0.f;
#pragma unroll
        for (int y = 0; y < 21; y++) {
            u0 += v[y] * phi[y]; u1 += v[y] * phi[21 + y]; u2 += v[y] * phi[42 + y];
        }
        u0 *= dy; u1 *= dy; u2 *= dy;
#pragma unroll
        for (int y = 0; y < 21; y++)
            sp[y][tid] = v[y] - (u0 * phi[y] + u1 * phi[21 + y] + u2 * phi[42 + y]);
    }
    __syncthreads();

    const float* c1 = trig, *s1 = trig + 180, *c2 = trig + 360, *s2 = trig + 540;
    const float inv = 1.f / 180.f, inv2 = 2.f / 180.f;
#pragma unroll 1
    for (int y = wid; y < 21; y += 6) {
        float q0 = 0.f, q1 = 0.f, q2 = 0.f, q3 = 0.f, q4 = 0.f;
#pragma unroll
        for (int t = 0; t < 6; t++) {
            int n = t * 32 + lane;
            if (n < W) {
                float xv = sp[y][n];
                q0 += xv; q1 += xv * c1[n]; q2 += xv * s1[n];
                q3 += xv * c2[n]; q4 += xv * s2[n];
            }
        }
#pragma unroll
        for (int o = 16; o; o >>= 1) {
            q0 += __shfl_xor_sync(~0u, q0, o); q1 += __shfl_xor_sync(~0u, q1, o);
            q2 += __shfl_xor_sync(~0u, q2, o); q3 += __shfl_xor_sync(~0u, q3, o);
            q4 += __shfl_xor_sync(~0u, q4, o);
        }
#pragma unroll
        for (int t = 0; t < 6; t++) {
            int n = t * 32 + lane;
            if (n < W)
                base[y * W + n] = sp[y][n] - q0 * inv
                    - inv2 * (q1 * c1[n] + q2 * s1[n] + q3 * c2[n] + q4 * s2[n]);
        }
    }
}

// ---------------- FC1 via tf32 mma, split-K=180 ----------------------------------
__global__ __launch_bounds__(256)
void fc1_mma(const float* __restrict__ act, const float* __restrict__ w,
             float* __restrict__ part)
{
    int tid = threadIdx.x, lane = tid & 31, wid = tid >> 5;
    int ks = blockIdx.x, jg = blockIdx.y;
    int r = lane >> 2, cc = lane & 3;
    int j0 = jg * 128 + wid * 16 + r, j1 = j0 + 8;
    bool ok0 = j0 < 500, ok1 = j1 < 500;
    const float* w0 = w + (size_t)j0 * FEAT;
    const float* w1 = w + (size_t)j1 * FEAT;
    const float* a0 = act + (size_t)r * FEAT;
    const float* a1 = a0 + (size_t)8 * FEAT;
    const float* a2 = a0 + (size_t)16 * FEAT;
    const float* a3 = a0 + (size_t)24 * FEAT;
    int kb = ks * KC2;
    float acc[4][4] = {};
#pragma unroll 2
    for (int k = kb; k < kb + KC2; k += 8) {
        uint32_t a[4];
        a[0] = ok0 ? tf32u(w0[k + cc]) : 0u;
        a[1] = ok1 ? tf32u(w1[k + cc]) : 0u;
        a[2] = ok0 ? tf32u(w0[k + 4 + cc]) : 0u;
        a[3] = ok1 ? tf32u(w1[k + 4 + cc]) : 0u;
        uint32_t bb[2];
        bb[0] = tf32u(a0[k + cc]); bb[1] = tf32u(a0[k + 4 + cc]); mma_tf32(acc[0], a, bb);
        bb[0] = tf32u(a1[k + cc]); bb[1] = tf32u(a1[k + 4 + cc]); mma_tf32(acc[1], a, bb);
        bb[0] = tf32u(a2[k + cc]); bb[1] = tf32u(a2[k + 4 + cc]); mma_tf32(acc[2], a, bb);
        bb[0] = tf32u(a3[k + cc]); bb[1] = tf32u(a3[k + 4 + cc]); mma_tf32(acc[3], a, bb);
    }
    float* pp = part + (size_t)(jg * NS2 + ks) * 4096;
    int jr = wid * 16 + r;
#pragma unroll
    for (int nt = 0; nt < 4; nt++) {
        int bc = nt * 8 + 2 * cc;
        pp[jr * 32 + bc]           = acc[nt][0];
        pp[jr * 32 + bc + 1]       = acc[nt][1];
        pp[(jr + 8) * 32 + bc]     = acc[nt][2];
        pp[(jr + 8) * 32 + bc + 1] = acc[nt][3];
    }
}

__global__ void fc1_reduce(const float* __restrict__ part, const float* __restrict__ bias,
                           float* __restrict__ h1)
{
    int idx = blockIdx.x * blockDim.x + threadIdx.x;
    if (idx >= 32 * 512) return;
    int b = idx & 31, j = idx >> 5;
    if (j >= 500) return;
    int jg = j >> 7, jr = j & 127;
    float s = bias[j];
    const float* pp = part + (size_t)jg * NS2 * 4096 + jr * 32 + b;
    for (int k = 0; k < NS2; k++) s += pp[(size_t)k * 4096];
    h1[b * 500 + j] = s;
}

__global__ void fc_small(const float* __restrict__ in, const float* __restrict__ w,
                         const float* __restrict__ bias, float* __restrict__ out,
                         int N, int K, int reluIn, int reluOut)
{
    int idx = blockIdx.x * blockDim.x + threadIdx.x;
    if (idx >= 32 * N) return;
    int b = idx / N, n = idx % N;
    float s = bias[n];
    const float* ip = in + b * K;
    const float* wp = w + n * K;
    for (int k = 0; k < K; k++) {
        float a = ip[k];
        if (reluIn) a = fmaxf(a, 0.f);
        s = fmaf(a, wp[k], s);
    }
    if (reluOut) s = fmaxf(s, 0.f);
    out[idx] = s;
}

// ---------------- host launcher ----------------
extern "C" void kernel_launch(void* const* d_in, const int* in_sizes, int n_in,
                              void* d_out, int out_size)
{
    const float* x    = (const float*)d_in[0];
    const float* w_in = (const float*)d_in[1];
    const float* b_in = (const float*)d_in[2];
    const float* w1 = (const float*)d_in[3],  *b1 = (const float*)d_in[4];
    const float* w2 = (const float*)d_in[5],  *b2 = (const float*)d_in[6];
    const float* w3 = (const float*)d_in[7],  *b3 = (const float*)d_in[8];
    const float* w4 = (const float*)d_in[9],  *b4 = (const float*)d_in[10];
    const float* w5 = (const float*)d_in[11], *b5 = (const float*)d_in[12];
    const float* wfc1 = (const float*)d_in[13], *bfc1 = (const float*)d_in[14];
    const float* wfc2 = (const float*)d_in[15], *bfc2 = (const float*)d_in[16];
    const float* wfc3 = (const float*)d_in[17], *bfc3 = (const float*)d_in[18];
    const float* wfc4 = (const float*)d_in[19], *bfc4 = (const float*)d_in[20];
    float* out = (float*)d_out;

    float *x1, *x2, *x3, *x4, *x5, *x6, *part, *h1, *h2, *h3, *phi, *trig;
    uint32_t* wfrag;
    cudaGetSymbolAddress((void**)&x1, g_x1);
    cudaGetSymbolAddress((void**)&x2, g_x2);
    cudaGetSymbolAddress((void**)&x3, g_x3);
    cudaGetSymbolAddress((void**)&x4, g_x4);
    cudaGetSymbolAddress((void**)&x5, g_x5);
    cudaGetSymbolAddress((void**)&x6, g_x6);
    cudaGetSymbolAddress((void**)&wfrag, g_wfrag);
    cudaGetSymbolAddress((void**)&part, g_part);
    cudaGetSymbolAddress((void**)&h1, g_h1);
    cudaGetSymbolAddress((void**)&h2, g_h2);
    cudaGetSymbolAddress((void**)&h3, g_h3);
    cudaGetSymbolAddress((void**)&phi, g_phi);
    cudaGetSymbolAddress((void**)&trig, g_trig);

    const int smem_c = 16000 * 4;   // 64000 B -> 2 CTAs/SM
    cudaFuncSetAttribute(conv_mma<64>,
                         cudaFuncAttributeMaxDynamicSharedMemorySize, smem_c);
    cudaFuncSetAttribute(conv_mma<128>,
                         cudaFuncAttributeMaxDynamicSharedMemorySize, smem_c);

    // L0: fused prologue (tables + A-frag pack)
    init_all<<<1600, 256>>>(w1, w2, w3, w4, w5, wfrag, phi, trig);
    // L1: conv_in (fp32, tiny)
    conv_in_k<<<(B * 64 * PIX + 255) / 256, 256>>>(x, w_in, b_in, x1);

    // L2-L6: tensor convs, N=192 full row; concat fused via dual-write
    dim3 gm(1, 21, B);
    conv_mma<64><<<gm, 256, smem_c>>>(x1, wfrag,          b1, x2, 64,  x6, 192, 128);
    conv_mma<64><<<gm, 256, smem_c>>>(x2, wfrag + 102400, b2, x3, 64,  x5, 128, 64);
    conv_mma<64><<<gm, 256, smem_c>>>(x3, wfrag + 204800, b3, x4, 64,  nullptr, 0, 0);
    conv_mma<64><<<gm, 256, smem_c>>>(x4, wfrag + 307200, b4, x5, 128, nullptr, 0, 0);
    conv_mma<128><<<dim3(2, 21, B), 256, smem_c>>>(x5, wfrag + 409600, b5, x6, 192,
                                                   nullptr, 0, 0);

    // L7: fused residual filters
    filter_fused<<<B * 192, 192>>>(x6, phi, trig);

    // FC stack
    fc1_mma<<<dim3(NS2, 4), 256>>>(x6, wfc1, part);
    fc1_reduce<<<64, 256>>>(part, bfc1, h1);
    fc_small<<<(32 * 200 + 255) / 256, 256>>>(h1, wfc2, bfc2, h2, 200, 500, 1, 1);
    fc_small<<<(32 * 50 + 255) / 256, 256>>>(h2, wfc3, bfc3, h3, 50, 200, 0, 1);
    fc_small<<<1, 64>>>(h3, wfc4, bfc4, out, 2, 50, 0, 0);
}

// round 15
// speedup vs baseline: 1.4544x; 1.3264x over previous
#include <cuda_runtime.h>
#include <cuda_bf16.h>
#include <math.h>
#include <stdint.h>

#define B 32
#define H 21
#define W 180
#define PIX (H*W)
#define FEAT (192*PIX)
#define NS2 180
#define KC2 (FEAT/NS2)
#define DPI 3.14159265358979323846

__device__ float g_x1[B*64*PIX];
__device__ float g_x2[B*64*PIX];
__device__ float g_x3[B*64*PIX];
__device__ float g_x4[B*64*PIX];
__device__ float g_x5[B*128*PIX];
__device__ float g_x6[B*192*PIX];
__device__ uint32_t g_wfrag[819200];
__device__ float g_part[4*NS2*4096];
__device__ float g_h1[B*500];
__device__ float g_h2[B*200];
__device__ float g_h3[B*50];
__device__ float g_phi[64];
__device__ float g_trig[720];

// ---------------- helpers ----------------
__device__ __forceinline__ uint32_t tf32u(float x) {
    uint32_t u; asm("cvt.rna.tf32.f32 %0, %1;" : "=r"(u) : "f"(x)); return u;
}
__device__ __forceinline__ float tf32f(float x) {
    return __uint_as_float(tf32u(x));
}
__device__ __forceinline__ void mma_tf32(float* c, const uint32_t* a, const uint32_t* b) {
    asm("mma.sync.aligned.m16n8k8.row.col.f32.tf32.tf32.f32 "
        "{%0,%1,%2,%3},{%4,%5,%6,%7},{%8,%9},{%0,%1,%2,%3};"
        : "+f"(c[0]), "+f"(c[1]), "+f"(c[2]), "+f"(c[3])
        : "r"(a[0]), "r"(a[1]), "r"(a[2]), "r"(a[3]), "r"(b[0]), "r"(b[1]));
}
__device__ __forceinline__ void mma_bf16(float* c, const uint32_t* a, const uint32_t* b) {
    asm("mma.sync.aligned.m16n8k16.row.col.f32.bf16.bf16.f32 "
        "{%0,%1,%2,%3},{%4,%5,%6,%7},{%8,%9},{%0,%1,%2,%3};"
        : "+f"(c[0]), "+f"(c[1]), "+f"(c[2]), "+f"(c[3])
        : "r"(a[0]), "r"(a[1]), "r"(a[2]), "r"(a[3]), "r"(b[0]), "r"(b[1]));
}
__device__ __forceinline__ void bf16split(float v, uint16_t& h, uint16_t& l) {
    __nv_bfloat16 hb = __float2bfloat16(v);
    float hf = __bfloat162float(hb);
    __nv_bfloat16 lb = __float2bfloat16(v - hf);
    h = __bfloat16_as_ushort(hb); l = __bfloat16_as_ushort(lb);
}

// ---------------- fused prologue: tables + bf16 A-frag pack ----------------------
__global__ void init_all(const float* __restrict__ w1, const float* __restrict__ w2,
                         const float* __restrict__ w3, const float* __restrict__ w4,
                         const float* __restrict__ w5, uint32_t* __restrict__ frag,
                         float* __restrict__ phi, float* __restrict__ trig)
{
    int idx = blockIdx.x * blockDim.x + threadIdx.x;
    if (idx == 0) {
        double beta = 2.28e-11, L = sqrt(51.0 / beta), spi = sqrt(DPI);
        double n0 = sqrt(spi), n1 = sqrt(2.0 * spi), n2 = sqrt(8.0 * spi);
        for (int i = 0; i < 21; i++) {
            double y = (20.0 - 2.0 * i) * 110000.0 / L;
            double e = exp(-y * y / 2.0);
            phi[i]      = (float)(e / n0);
            phi[21 + i] = (float)(e * 2.0 * y / n1);
            phi[42 + i] = (float)(e * (4.0 * y * y - 2.0) / n2);
        }
        phi[63] = (float)(2.0 * 110000.0 / L);
        for (int n = 0; n < 180; n++) {
            double t = 2.0 * DPI * n / 180.0;
            trig[n] = (float)cos(t); trig[180 + n] = (float)sin(t);
            trig[360 + n] = (float)cos(2 * t); trig[540 + n] = (float)sin(2 * t);
        }
    }
    if (idx >= 409600) return;
    const float* w; int IC, t, mh = 0, base, WSZ;
    if (idx < 204800) {
        int l = idx / 51200; t = idx % 51200;
        w = l == 0 ? w1 : l == 1 ? w2 : l == 2 ? w3 : w4;
        IC = 64; base = l * 102400; WSZ = 51200;
    } else {
        int q = idx - 204800;
        mh = q / 102400; t = q % 102400;
        w = w5; IC = 128; base = 409600 + mh * 204800; WSZ = 102400;
    }
    int CH = IC / 16, P = CH * 512;
    int kpos = t / P; int r = t % P;
    int ck = r / 512; int r2 = r % 512;
    int mtile = r2 >> 7; int ln = (r2 >> 2) & 31; int reg = r2 & 3;
    int row = (ln >> 2) + (reg & 1) * 8;
    int k0  = 2 * (ln & 3) + (reg >> 1) * 8;
    int oc = mh * 64 + mtile * 16 + row;
    int ic = ck * 16 + k0;
    float v0 = w[((size_t)oc * IC + ic) * 25 + kpos];
    float v1 = w[((size_t)oc * IC + ic + 1) * 25 + kpos];
    uint16_t h0, l0, h1, l1;
    bf16split(v0, h0, l0); bf16split(v1, h1, l1);
    frag[base + t]       = (uint32_t)h0 | ((uint32_t)h1 << 16);
    frag[base + WSZ + t] = (uint32_t)l0 | ((uint32_t)l1 << 16);
}

// ---------------- conv_in: 1->64, naive fp32 -------------------------------------
__global__ void conv_in_k(const float* __restrict__ x, const float* __restrict__ w,
                          const float* __restrict__ bias, float* __restrict__ out)
{
    int idx = blockIdx.x * blockDim.x + threadIdx.x;
    if (idx >= B * 64 * PIX) return;
    int px = idx % PIX, oc = (idx / PIX) & 63, b = idx / (64 * PIX);
    int y = px / W, xx = px % W;
    const float* ip = x + (size_t)b * PIX;
    const float* wp = w + oc * 25;
    float s = bias[oc];
#pragma unroll
    for (int kh = 0; kh < 5; kh++) {
        int gy = y + kh - 2;
        if (gy < 0 || gy >= H) continue;
#pragma unroll
        for (int kw = 0; kw < 5; kw++) {
            int gx = xx + kw - 2;
            if (gx >= 0 && gx < W) s = fmaf(ip[gy * W + gx], wp[kh * 5 + kw], s);
        }
    }
    out[idx] = fmaxf(s, 0.f);
}

// ---------------- tensor conv (unchanged from R14, passing) ----------------------
template<int IC>
__global__ __launch_bounds__(256, 2)
void conv_mma(const float* __restrict__ in, const uint32_t* __restrict__ wfrag,
              const float* __restrict__ bias,
              float* __restrict__ out, int outCtot,
              float* __restrict__ out2, int out2Ctot, int out2Off)
{
    constexpr int CH = IC / 16;
    constexpr int WSZ = 25 * CH * 512;
    constexpr int RS = 200, XS = 5 * RS;
    extern __shared__ uint32_t smu[];
    uint32_t* sInH = smu;
    uint32_t* sInL = smu + 8000;

    int tid = threadIdx.x, lane = tid & 31, warpId = tid >> 5;
    int wm = warpId >> 2, wn = warpId & 3;
    int mh = blockIdx.x;
    int y = blockIdx.y, b = blockIdx.z;
    const uint32_t* wH = wfrag + mh * 2 * WSZ;
    const uint32_t* wL = wH + WSZ;

    float c[2][6][4] = {};
    int p = warpId;

#pragma unroll 1
    for (int ch = 0; ch < CH; ch++) {
        __syncthreads();
        {
            const float* in0 = in + (size_t)(b * IC + ch * 16 + 2 * p) * PIX;
            const float* in1 = in0 + PIX;
            uint32_t* dH = sInH + p * XS;
            uint32_t* dL = sInL + p * XS;
#pragma unroll
            for (int r = 0; r < 5; r++) {
                int gy = y + r - 2;
                bool okY = (gy >= 0 && gy < H);
                const float* r0 = in0 + gy * W - 2;
                const float* r1 = in1 + gy * W - 2;
#pragma unroll
                for (int xx = lane; xx < RS; xx += 32) {
                    int gx = xx - 2;
                    float v0 = 0.f, v1 = 0.f;
                    if (okY && gx >= 0 && gx < W) { v0 = r0[xx]; v1 = r1[xx]; }
                    uint16_t h0, l0, h1, l1;
                    bf16split(v0, h0, l0); bf16split(v1, h1, l1);
                    dH[r * RS + xx] = (uint32_t)h0 | ((uint32_t)h1 << 16);
                    dL[r * RS + xx] = (uint32_t)l0 | ((uint32_t)l1 << 16);
                }
            }
        }
        __syncthreads();
#pragma unroll 1
        for (int kh = 0; kh < 5; kh++) {
#pragma unroll 1
            for (int kw = 0; kw < 5; kw++) {
                uint32_t ah[2][4], al[2][4];
                int wbase = ((kh * 5 + kw) * CH + ch) * 512 + lane * 4;
#pragma unroll
                for (int mt = 0; mt < 2; mt++) {
                    int o = wbase + (wm * 2 + mt) * 128;
                    *(uint4*)ah[mt] = *(const uint4*)&wH[o];
                    *(uint4*)al[mt] = *(const uint4*)&wL[o];
                }
                int bbase = (lane & 3) * XS + kh * RS + wn * 48 + (lane >> 2) + kw;
                uint32_t bh[6][2], bl[6][2];
#pragma unroll
                for (int nt = 0; nt < 6; nt++) {
                    int bi = bbase + nt * 8;
                    bh[nt][0] = sInH[bi]; bh[nt][1] = sInH[bi + 4 * XS];
                    bl[nt][0] = sInL[bi]; bl[nt][1] = sInL[bi + 4 * XS];
                }
#pragma unroll
                for (int mt = 0; mt < 2; mt++)
#pragma unroll
                    for (int nt = 0; nt < 6; nt++)
                        mma_bf16(c[mt][nt], ah[mt], bh[nt]);
#pragma unroll
                for (int mt = 0; mt < 2; mt++)
#pragma unroll
                    for (int nt = 0; nt < 6; nt++)
                        mma_bf16(c[mt][nt], ah[mt], bl[nt]);
#pragma unroll
                for (int mt = 0; mt < 2; mt++)
#pragma unroll
                    for (int nt = 0; nt < 6; nt++)
                        mma_bf16(c[mt][nt], al[mt], bh[nt]);
            }
        }
    }

    int ocL = mh * 64 + wm * 32;
#pragma unroll
    for (int mt = 0; mt < 2; mt++) {
        int ocRow = ocL + mt * 16 + (lane >> 2);
        float bv0 = bias[ocRow], bv8 = bias[ocRow + 8];
#pragma unroll
        for (int nt = 0; nt < 6; nt++) {
            int x = wn * 48 + nt * 8 + (lane & 3) * 2;
            if (x < W) {
                float2 v0 = make_float2(fmaxf(c[mt][nt][0] + bv0, 0.f),
                                        fmaxf(c[mt][nt][1] + bv0, 0.f));
                float2 v1 = make_float2(fmaxf(c[mt][nt][2] + bv8, 0.f),
                                        fmaxf(c[mt][nt][3] + bv8, 0.f));
                size_t o0 = ((size_t)(b * outCtot + ocRow) * H + y) * W + x;
                size_t o1 = o0 + (size_t)8 * H * W;
                *(float2*)&out[o0] = v0;
                *(float2*)&out[o1] = v1;
                if (out2) {
                    size_t q0 = ((size_t)(b * out2Ctot + out2Off + ocRow) * H + y) * W + x;
                    size_t q1 = q0 + (size_t)8 * H * W;
                    *(float2*)&out2[q0] = v0;
                    *(float2*)&out2[q1] = v1;
                }
            }
        }
    }
}

// ---------------- fused Hermite + Fourier residual, single pass ------------------
__global__ __launch_bounds__(192)
void filter_fused(float* __restrict__ x, const float* __restrict__ phi,
                  const float* __restrict__ trig)
{
    __shared__ float sp[21][181];
    int tid = threadIdx.x, wid = tid >> 5, lane = tid & 31;
    float* base = x + (size_t)blockIdx.x * PIX;

    if (tid < 180) {
        float v[21];
#pragma unroll
        for (int y = 0; y < 21; y++) v[y] = base[y * W + tid];
        float dy = phi[63], u0 = 0.f, u1 = 0.f, u2 = 0.f;
#pragma unroll
        for (int y = 0; y < 21; y++) {
            u0 += v[y] * phi[y]; u1 += v[y] * phi[21 + y]; u2 += v[y] * phi[42 + y];
        }
        u0 *= dy; u1 *= dy; u2 *= dy;
#pragma unroll
        for (int y = 0; y < 21; y++)
            sp[y][tid] = v[y] - (u0 * phi[y] + u1 * phi[21 + y] + u2 * phi[42 + y]);
    }
    __syncthreads();

    const float* c1 = trig, *s1 = trig + 180, *c2 = trig + 360, *s2 = trig + 540;
    const float inv = 1.f / 180.f, inv2 = 2.f / 180.f;
#pragma unroll 1
    for (int y = wid; y < 21; y += 6) {
        float q0 = 0.f, q1 = 0.f, q2 = 0.f, q3 = 0.f, q4 = 0.f;
#pragma unroll
        for (int t = 0; t < 6; t++) {
            int n = t * 32 + lane;
            if (n < W) {
                float xv = sp[y][n];
                q0 += xv; q1 += xv * c1[n]; q2 += xv * s1[n];
                q3 += xv * c2[n]; q4 += xv * s2[n];
            }
        }
#pragma unroll
        for (int o = 16; o; o >>= 1) {
            q0 += __shfl_xor_sync(~0u, q0, o); q1 += __shfl_xor_sync(~0u, q1, o);
            q2 += __shfl_xor_sync(~0u, q2, o); q3 += __shfl_xor_sync(~0u, q3, o);
            q4 += __shfl_xor_sync(~0u, q4, o);
        }
#pragma unroll
        for (int t = 0; t < 6; t++) {
            int n = t * 32 + lane;
            if (n < W)
                base[y * W + n] = sp[y][n] - q0 * inv
                    - inv2 * (q1 * c1[n] + q2 * s1[n] + q3 * c2[n] + q4 * s2[n]);
        }
    }
}

// ---------------- FC1 v2: smem-staged tf32 GEMM, double-buffered -----------------
// Block: 256 thr, j-tile 128, K-chunk 4032 in 32k tiles. W/A staged via LDG.128,
// cvt.rna once at staging. smem [j][36] and [k][36] -> conflict-free frag LDS.
__global__ __launch_bounds__(256)
void fc1_v2(const float* __restrict__ act, const float* __restrict__ w,
            float* __restrict__ part)
{
    __shared__ float sW[2][128 * 36];   // 36864 B
    __shared__ float sA[2][32 * 36];    //  9216 B
    int tid = threadIdx.x, lane = tid & 31, wid = tid >> 5;
    int ks = blockIdx.x, jg = blockIdx.y;
    int kb = ks * KC2, jg0 = jg * 128;

    int jbase = tid >> 3;       // 0..31
    int kq = tid & 7;           // 0..7 (float4 slot)
    int bq = tid >> 3;          // act batch row 0..31
    bool okj[4];
    const float* wrow[4];
#pragma unroll
    for (int i = 0; i < 4; i++) {
        int jglob = jg0 + jbase + 32 * i;
        okj[i] = jglob < 500;
        wrow[i] = w + (size_t)(okj[i] ? jglob : 0) * FEAT;
    }
    const float* arow = act + (size_t)bq * FEAT;

    float4 wr[4], ar;
    auto ldg = [&](int kt) {
        int koff = kb + kt * 32 + kq * 4;
#pragma unroll
        for (int i = 0; i < 4; i++)
            wr[i] = okj[i] ? *(const float4*)&wrow[i][koff]
                           : make_float4(0.f, 0.f, 0.f, 0.f);
        ar = *(const float4*)&arow[koff];
    };
    auto sts = [&](int buf) {
#pragma unroll
        for (int i = 0; i < 4; i++) {
            float* d = &sW[buf][(jbase + 32 * i) * 36 + kq * 4];
            d[0] = tf32f(wr[i].x); d[1] = tf32f(wr[i].y);
            d[2] = tf32f(wr[i].z); d[3] = tf32f(wr[i].w);
        }
        sA[buf][(kq * 4 + 0) * 36 + bq] = tf32f(ar.x);
        sA[buf][(kq * 4 + 1) * 36 + bq] = tf32f(ar.y);
        sA[buf][(kq * 4 + 2) * 36 + bq] = tf32f(ar.z);
        sA[buf][(kq * 4 + 3) * 36 + bq] = tf32f(ar.w);
    };

    float acc[4][4] = {};
    int r = lane >> 2, cc = lane & 3;
    int row0 = wid * 16 + r;

    ldg(0);
    sts(0);
    __syncthreads();
#pragma unroll 1
    for (int kt = 0; kt < 126; kt++) {
        int cur = kt & 1;
        if (kt + 1 < 126) ldg(kt + 1);
#pragma unroll
        for (int k8 = 0; k8 < 4; k8++) {
            int k = k8 * 8;
            uint32_t a[4];
            a[0] = __float_as_uint(sW[cur][row0 * 36 + k + cc]);
            a[1] = __float_as_uint(sW[cur][(row0 + 8) * 36 + k + cc]);
            a[2] = __float_as_uint(sW[cur][row0 * 36 + k + 4 + cc]);
            a[3] = __float_as_uint(sW[cur][(row0 + 8) * 36 + k + 4 + cc]);
#pragma unroll
            for (int nt = 0; nt < 4; nt++) {
                uint32_t bf[2];
                int n = nt * 8 + r;
                bf[0] = __float_as_uint(sA[cur][(k + cc) * 36 + n]);
                bf[1] = __float_as_uint(sA[cur][(k + 4 + cc) * 36 + n]);
                mma_tf32(acc[nt], a, bf);
            }
        }
        if (kt + 1 < 126) {
            __syncthreads();
            sts((kt + 1) & 1);
            __syncthreads();
        }
    }

    float* pp = part + (size_t)(jg * NS2 + ks) * 4096;
    int jr = wid * 16 + r;
#pragma unroll
    for (int nt = 0; nt < 4; nt++) {
        int bc = nt * 8 + 2 * cc;
        pp[jr * 32 + bc]           = acc[nt][0];
        pp[jr * 32 + bc + 1]       = acc[nt][1];
        pp[(jr + 8) * 32 + bc]     = acc[nt][2];
        pp[(jr + 8) * 32 + bc + 1] = acc[nt][3];
    }
}

__global__ void fc1_reduce(const float* __restrict__ part, const float* __restrict__ bias,
                           float* __restrict__ h1)
{
    int idx = blockIdx.x * blockDim.x + threadIdx.x;
    if (idx >= 32 * 512) return;
    int b = idx & 31, j = idx >> 5;
    if (j >= 500) return;
    int jg = j >> 7, jr = j & 127;
    float s = bias[j];
    const float* pp = part + (size_t)jg * NS2 * 4096 + jr * 32 + b;
    for (int k = 0; k < NS2; k++) s += pp[(size_t)k * 4096];
    h1[b * 500 + j] = s;
}

__global__ void fc_small(const float* __restrict__ in, const float* __restrict__ w,
                         const float* __restrict__ bias, float* __restrict__ out,
                         int N, int K, int reluIn, int reluOut)
{
    int idx = blockIdx.x * blockDim.x + threadIdx.x;
    if (idx >= 32 * N) return;
    int b = idx / N, n = idx % N;
    float s = bias[n];
    const float* ip = in + b * K;
    const float* wp = w + n * K;
    for (int k = 0; k < K; k++) {
        float a = ip[k];
        if (reluIn) a = fmaxf(a, 0.f);
        s = fmaf(a, wp[k], s);
    }
    if (reluOut) s = fmaxf(s, 0.f);
    out[idx] = s;
}

// ---------------- host launcher ----------------
extern "C" void kernel_launch(void* const* d_in, const int* in_sizes, int n_in,
                              void* d_out, int out_size)
{
    const float* x    = (const float*)d_in[0];
    const float* w_in = (const float*)d_in[1];
    const float* b_in = (const float*)d_in[2];
    const float* w1 = (const float*)d_in[3],  *b1 = (const float*)d_in[4];
    const float* w2 = (const float*)d_in[5],  *b2 = (const float*)d_in[6];
    const float* w3 = (const float*)d_in[7],  *b3 = (const float*)d_in[8];
    const float* w4 = (const float*)d_in[9],  *b4 = (const float*)d_in[10];
    const float* w5 = (const float*)d_in[11], *b5 = (const float*)d_in[12];
    const float* wfc1 = (const float*)d_in[13], *bfc1 = (const float*)d_in[14];
    const float* wfc2 = (const float*)d_in[15], *bfc2 = (const float*)d_in[16];
    const float* wfc3 = (const float*)d_in[17], *bfc3 = (const float*)d_in[18];
    const float* wfc4 = (const float*)d_in[19], *bfc4 = (const float*)d_in[20];
    float* out = (float*)d_out;

    float *x1, *x2, *x3, *x4, *x5, *x6, *part, *h1, *h2, *h3, *phi, *trig;
    uint32_t* wfrag;
    cudaGetSymbolAddress((void**)&x1, g_x1);
    cudaGetSymbolAddress((void**)&x2, g_x2);
    cudaGetSymbolAddress((void**)&x3, g_x3);
    cudaGetSymbolAddress((void**)&x4, g_x4);
    cudaGetSymbolAddress((void**)&x5, g_x5);
    cudaGetSymbolAddress((void**)&x6, g_x6);
    cudaGetSymbolAddress((void**)&wfrag, g_wfrag);
    cudaGetSymbolAddress((void**)&part, g_part);
    cudaGetSymbolAddress((void**)&h1, g_h1);
    cudaGetSymbolAddress((void**)&h2, g_h2);
    cudaGetSymbolAddress((void**)&h3, g_h3);
    cudaGetSymbolAddress((void**)&phi, g_phi);
    cudaGetSymbolAddress((void**)&trig, g_trig);

    const int smem_c = 16000 * 4;   // 64000 B -> 2 CTAs/SM
    cudaFuncSetAttribute(conv_mma<64>,
                         cudaFuncAttributeMaxDynamicSharedMemorySize, smem_c);
    cudaFuncSetAttribute(conv_mma<128>,
                         cudaFuncAttributeMaxDynamicSharedMemorySize, smem_c);

    init_all<<<1600, 256>>>(w1, w2, w3, w4, w5, wfrag, phi, trig);
    conv_in_k<<<(B * 64 * PIX + 255) / 256, 256>>>(x, w_in, b_in, x1);

    dim3 gm(1, 21, B);
    conv_mma<64><<<gm, 256, smem_c>>>(x1, wfrag,          b1, x2, 64,  x6, 192, 128);
    conv_mma<64><<<gm, 256, smem_c>>>(x2, wfrag + 102400, b2, x3, 64,  x5, 128, 64);
    conv_mma<64><<<gm, 256, smem_c>>>(x3, wfrag + 204800, b3, x4, 64,  nullptr, 0, 0);
    conv_mma<64><<<gm, 256, smem_c>>>(x4, wfrag + 307200, b4, x5, 128, nullptr, 0, 0);
    conv_mma<128><<<dim3(2, 21, B), 256, smem_c>>>(x5, wfrag + 409600, b5, x6, 192,
                                                   nullptr, 0, 0);

    filter_fused<<<B * 192, 192>>>(x6, phi, trig);

    fc1_v2<<<dim3(NS2, 4), 256>>>(x6, wfc1, part);
    fc1_reduce<<<64, 256>>>(part, bfc1, h1);
    fc_small<<<(32 * 200 + 255) / 256, 256>>>(h1, wfc2, bfc2, h2, 200, 500, 1, 1);
    fc_small<<<(32 * 50 + 255) / 256, 256>>>(h2, wfc3, bfc3, h3, 50, 200, 0, 1);
    fc_small<<<1, 64>>>(h3, wfc4, bfc4, out, 2, 50, 0, 0);
}